// round 10
// baseline (speedup 1.0000x reference)
#include <cuda_runtime.h>
#include <cuda_fp16.h>
#include <cstdint>

// Problem constants
#define B_SZ   256
#define LDIM   257                 // N+1
#define M_MAP  66049               // 257*257  (GEMM K)
#define H_DIM  512
#define C_OUT  4

// GEMM tiling (legacy fp16 mma m16n8k16)
#define BM 256                     // full batch
#define BN 128                     // 4 N tiles
#define BK 32                      // 2 k16 steps per chunk
#define SPLITS 35                  // 2065 k32-chunks = 35 * 59
#define CPS 59

// smem geometry
#define AROW 40                    // halfs per A row (32 + 8 pad) = 80B
#define BROW 36                    // floats per B row (32 + 4 pad) = 144B
#define BSTAGE_BYTES (BN * BROW * 4)     // 18432
#define ABUF_BYTES   (BM * AROW * 2)     // 20480
#define SM_B   0
#define SM_A   (3 * BSTAGE_BYTES)                 // 55296
#define SM_EB  (SM_A + 2 * ABUF_BYTES)            // 96256
#define SM_B1  (SM_EB + 264 * 4)                  // 97312
#define SMEM_BYTES (SM_B1 + 264 * 4)              // 98368

// Scratch
__device__ __align__(16) uint2 g_tbl[LDIM * B_SZ];                     // fp16 (Ea,Pa),(A1,Ra)
__device__ __align__(16) float g_part[(size_t)SPLITS * B_SZ * H_DIM];  // split-K partials
__device__ float g_consts[5];

__device__ __forceinline__ float frcp(float x) {
    float r; asm("rcp.approx.f32 %0, %1;" : "=f"(r) : "f"(x)); return r;
}
__device__ __forceinline__ uint32_t smem_u32(const void* p) {
    return (uint32_t)__cvta_generic_to_shared(p);
}
// 4-byte cp.async (fp32-safe alignment); src_bytes 0 -> zero-fill
__device__ __forceinline__ void cp4z(uint32_t dst, const float* src, int src_bytes) {
    asm volatile("cp.async.ca.shared.global [%0], [%1], 4, %2;\n" :: "r"(dst), "l"(src), "r"(src_bytes));
}
// pack two fp32 -> half2 {low=lo, high=hi}
__device__ __forceinline__ uint32_t pack_h2(float lo, float hi) {
    uint32_t u;
    asm("cvt.rn.f16x2.f32 %0, %1, %2;" : "=r"(u) : "f"(hi), "f"(lo));
    return u;
}
__device__ __forceinline__ float2 unpack_h2(uint32_t u) {
    __half2 h = *reinterpret_cast<__half2*>(&u);
    return __half22float2(h);
}

// ---------------------------------------------------------------------------
// Phase 0: fold 1x1-conv + eval-mode BN
// ---------------------------------------------------------------------------
__global__ void prep_kernel(const float* __restrict__ conv_w, const float* __restrict__ conv_b,
                            const float* __restrict__ bn_g,  const float* __restrict__ bn_b,
                            const float* __restrict__ bn_m,  const float* __restrict__ bn_v) {
    if (threadIdx.x == 0) {
        float s = bn_g[0] * rsqrtf(bn_v[0] + 1e-5f);
        g_consts[0] = conv_w[0] * s;
        g_consts[1] = conv_w[1] * s;
        g_consts[2] = conv_w[2] * s;
        g_consts[3] = conv_w[3] * s;
        g_consts[4] = (conv_b[0] - bn_m[0]) * s + bn_b[0];
    }
}

// ---------------------------------------------------------------------------
// Phase 0b: per-(j,b) transcendental table (fp16): (Ea, Pa), (A1, Ra)
// ---------------------------------------------------------------------------
__global__ void pre_kernel(const float* __restrict__ x1) {
    const int j = blockIdx.x;     // 0..256
    const int b = threadIdx.x;    // 0..255
    const float a0 = (j == 0) ? 0.0f : x1[b * (LDIM - 1) + j - 1];
    const float a1 = (j == 0) ? 1.0f : a0;
    const float Ea = __expf(-a0);
    const float Pa = frcp(Ea);
    float Ra = frcp(a1 + 1e-10f);
    Ra = fmaxf(fminf(Ra, 60000.0f), -60000.0f);   // fp16-safe; sigmoid saturated anyway
    uint2 v;
    v.x = pack_h2(Ea, Pa);
    v.y = pack_h2(a1, Ra);
    g_tbl[j * B_SZ + b] = v;
}

// ---------------------------------------------------------------------------
// Fused A-tile producer: compute A[b, k0..k0+31] in fp16 directly into smem.
// Thread t: k-pair kp = t&15 (k = k0+2kp, +1), b = (t>>4)*8 .. +7.
// ---------------------------------------------------------------------------
__device__ __forceinline__ void produce_A(char* Abuf, int c,
                                          const float* __restrict__ sEb,
                                          const float* __restrict__ sB1,
                                          float c0, float c1, float c2, float c3, float cb,
                                          int tid) {
    const int k0 = c * BK;
    const int kp = tid & 15;
    const int bb = (tid >> 4) * 8;
    const int ke = k0 + kp * 2;
    const int ko = ke + 1;
    const bool ve = ke < M_MAP;
    const bool vo = ko < M_MAP;
    const int ie = ve ? ke / LDIM : 0;
    const int io = vo ? ko / LDIM : 0;
    const int je = ve ? ke - ie * LDIM : 0;
    const int jo = vo ? ko - io * LDIM : 0;
    const float Ebe = sEb[ie], B1e = sB1[ie];
    const float Ebo = sEb[io], B1o = sB1[io];

    const uint4* __restrict__ T = reinterpret_cast<const uint4*>(g_tbl);
    uint4 te[4], to[4];
    const int base_e = je * (B_SZ / 2) + (bb >> 1);
    const int base_o = jo * (B_SZ / 2) + (bb >> 1);
#pragma unroll
    for (int q = 0; q < 4; q++) te[q] = T[base_e + q];
#pragma unroll
    for (int q = 0; q < 4; q++) to[q] = T[base_o + q];

    __half* Ah = reinterpret_cast<__half*>(Abuf);
#pragma unroll
    for (int q = 0; q < 4; q++) {
#pragma unroll
        for (int h = 0; h < 2; h++) {
            const int b = bb + q * 2 + h;
            float y_e = 0.0f, y_o = 0.0f;
            if (ve) {
                const float2 eap = unpack_h2(h ? te[q].z : te[q].x);
                const float2 a1r = unpack_h2(h ? te[q].w : te[q].y);
                const float xadd = frcp(1.0f + Ebe * eap.x);
                const float xsub = frcp(1.0f + Ebe * eap.y);
                const float xpro = frcp(1.0f + __expf(-B1e * a1r.x));
                const float xdiv = frcp(1.0f + __expf(-B1e * a1r.y));
                y_e = c0 * xadd + c1 * xsub + c2 * xpro + c3 * xdiv + cb;
                y_e = (y_e >= 0.0f) ? y_e : 0.1f * y_e;
            }
            if (vo) {
                const float2 eap = unpack_h2(h ? to[q].z : to[q].x);
                const float2 a1r = unpack_h2(h ? to[q].w : to[q].y);
                const float xadd = frcp(1.0f + Ebo * eap.x);
                const float xsub = frcp(1.0f + Ebo * eap.y);
                const float xpro = frcp(1.0f + __expf(-B1o * a1r.x));
                const float xdiv = frcp(1.0f + __expf(-B1o * a1r.y));
                y_o = c0 * xadd + c1 * xsub + c2 * xpro + c3 * xdiv + cb;
                y_o = (y_o >= 0.0f) ? y_o : 0.1f * y_o;
            }
            *reinterpret_cast<uint32_t*>(&Ah[b * AROW + kp * 2]) = pack_h2(y_e, y_o);
        }
    }
}

// ---------------------------------------------------------------------------
// B tile loader (unchanged from round 9, B-only stages)
// ---------------------------------------------------------------------------
__device__ __forceinline__ void load_B(char* sm, int stage, int gchunk, int bn0,
                                       const float* __restrict__ W, int tid) {
    const int k0 = gchunk * BK;
    uint32_t sB = smem_u32(sm + SM_B + stage * BSTAGE_BYTES);
#pragma unroll
    for (int r = 0; r < 8; r++) {
        int flat = tid + r * 512;
        int n = flat >> 5, k = flat & 31;
        int ke = k0 + k;
        int bytes = (ke < M_MAP) ? 4 : 0;
        const float* src = &W[(size_t)(bn0 + n) * M_MAP + (bytes ? ke : 0)];
        cp4z(sB + (n * BROW + k) * 4, src, bytes);
    }
}

__device__ __forceinline__ void mma_f16(float c[4], const uint32_t a[4], const uint32_t b[2]) {
    asm volatile(
        "mma.sync.aligned.m16n8k16.row.col.f32.f16.f16.f32 "
        "{%0,%1,%2,%3}, {%4,%5,%6,%7}, {%8,%9}, {%0,%1,%2,%3};\n"
        : "+f"(c[0]), "+f"(c[1]), "+f"(c[2]), "+f"(c[3])
        : "r"(a[0]), "r"(a[1]), "r"(a[2]), "r"(a[3]), "r"(b[0]), "r"(b[1]));
}

// ---------------------------------------------------------------------------
// Phase 1+2 fused: split-K fp16 GEMM with in-kernel activation producer.
// ---------------------------------------------------------------------------
__global__ void __launch_bounds__(512, 1) gemm_kernel(const float* __restrict__ W,
                                                      const float* __restrict__ x3) {
    extern __shared__ char sm[];
    float* sEb = reinterpret_cast<float*>(sm + SM_EB);
    float* sB1 = reinterpret_cast<float*>(sm + SM_B1);

    const int bn0   = blockIdx.x * BN;     // 4 N tiles
    const int split = blockIdx.y;          // 35 K splits
    const int cbeg  = split * CPS;

    const int tid  = threadIdx.x;
    const int wid  = tid >> 5, lane = tid & 31;
    const int wm   = wid & 3,  wn   = wid >> 2;    // 4 x 4
    const int g    = lane >> 2, tg  = lane & 3;

    // x3-side tables
    if (tid < LDIM) {
        const float b0 = (tid == 0) ? 0.0f : x3[tid - 1];
        sEb[tid] = __expf(-b0);
        sB1[tid] = (tid == 0) ? 1.0f : b0;
    }
    const float c0 = g_consts[0], c1 = g_consts[1];
    const float c2 = g_consts[2], c3 = g_consts[3];
    const float cb = g_consts[4];
    __syncthreads();

    float acc[4][4][4];
#pragma unroll
    for (int mi = 0; mi < 4; mi++)
#pragma unroll
        for (int ni = 0; ni < 4; ni++)
#pragma unroll
            for (int q = 0; q < 4; q++) acc[mi][ni][q] = 0.0f;

    // prologue: produce A(cbeg) into buf0; start B pipeline
    produce_A(sm + SM_A, cbeg, sEb, sB1, c0, c1, c2, c3, cb, tid);
    load_B(sm, 0, cbeg + 0, bn0, W, tid);
    asm volatile("cp.async.commit_group;\n" ::: "memory");
    load_B(sm, 1, cbeg + 1, bn0, W, tid);
    asm volatile("cp.async.commit_group;\n" ::: "memory");

    for (int cc = 0; cc < CPS; ++cc) {
        asm volatile("cp.async.wait_group 1;\n" ::: "memory");
        __syncthreads();

        if (cc + 2 < CPS)
            load_B(sm, (cc + 2) % 3, cbeg + cc + 2, bn0, W, tid);
        asm volatile("cp.async.commit_group;\n" ::: "memory");

        const __half* Sa = reinterpret_cast<const __half*>(sm + SM_A + (cc & 1) * ABUF_BYTES);
        const float*  Sb = reinterpret_cast<const float*>(sm + SM_B + (cc % 3) * BSTAGE_BYTES);

#pragma unroll
        for (int ks = 0; ks < 2; ++ks) {               // two k16 steps
            uint32_t a[4][4], bfr[4][2];
#pragma unroll
            for (int mi = 0; mi < 4; mi++) {
                const int r0 = wm * 64 + mi * 16 + g;
                const int kb = ks * 16 + tg * 2;
                a[mi][0] = *reinterpret_cast<const uint32_t*>(&Sa[(r0    ) * AROW + kb]);
                a[mi][1] = *reinterpret_cast<const uint32_t*>(&Sa[(r0 + 8) * AROW + kb]);
                a[mi][2] = *reinterpret_cast<const uint32_t*>(&Sa[(r0    ) * AROW + kb + 8]);
                a[mi][3] = *reinterpret_cast<const uint32_t*>(&Sa[(r0 + 8) * AROW + kb + 8]);
            }
#pragma unroll
            for (int ni = 0; ni < 4; ni++) {
                const int n0 = wn * 32 + ni * 8 + g;
                const int kb = ks * 16 + tg * 2;
                const float2 f01 = *reinterpret_cast<const float2*>(&Sb[n0 * BROW + kb]);
                const float2 f23 = *reinterpret_cast<const float2*>(&Sb[n0 * BROW + kb + 8]);
                bfr[ni][0] = pack_h2(f01.x, f01.y);
                bfr[ni][1] = pack_h2(f23.x, f23.y);
            }
#pragma unroll
            for (int mi = 0; mi < 4; mi++)
#pragma unroll
                for (int ni = 0; ni < 4; ni++)
                    mma_f16(acc[mi][ni], a[mi], bfr[ni]);
        }

        // produce A(cc+1) into the other buffer while tensor pipe drains
        if (cc + 1 < CPS)
            produce_A(sm + SM_A + ((cc + 1) & 1) * ABUF_BYTES, cbeg + cc + 1,
                      sEb, sB1, c0, c1, c2, c3, cb, tid);
    }

    // Deterministic partial store
    float* __restrict__ P = g_part + (size_t)split * (B_SZ * H_DIM);
#pragma unroll
    for (int mi = 0; mi < 4; mi++) {
#pragma unroll
        for (int ni = 0; ni < 4; ni++) {
            const int row = wm * 64 + mi * 16 + g;
            const int col = bn0 + wn * 32 + ni * 8 + tg * 2;
            *reinterpret_cast<float2*>(&P[(size_t)row * H_DIM + col]) =
                make_float2(acc[mi][ni][0], acc[mi][ni][1]);
            *reinterpret_cast<float2*>(&P[(size_t)(row + 8) * H_DIM + col]) =
                make_float2(acc[mi][ni][2], acc[mi][ni][3]);
        }
    }
}

// ---------------------------------------------------------------------------
// Phase 3: reduce 35 splits + bias -> ReLU -> 512->4 head
// ---------------------------------------------------------------------------
__global__ void __launch_bounds__(512) head_kernel(const float* __restrict__ fc_b,
                                                   const float* __restrict__ out_w,
                                                   const float* __restrict__ out_b,
                                                   float* __restrict__ out) {
    const int b = blockIdx.x;
    const int h = threadIdx.x;
    const int wid = h >> 5, lane = h & 31;

    float v = 0.0f;
#pragma unroll
    for (int sp = 0; sp < SPLITS; ++sp)
        v += g_part[(size_t)sp * (B_SZ * H_DIM) + (size_t)b * H_DIM + h];
    v += fc_b[h];
    v = fmaxf(v, 0.0f);

    float p[4];
#pragma unroll
    for (int c = 0; c < 4; ++c) p[c] = v * out_w[c * H_DIM + h];

#pragma unroll
    for (int off = 16; off > 0; off >>= 1)
#pragma unroll
        for (int c = 0; c < 4; ++c) p[c] += __shfl_down_sync(0xffffffffu, p[c], off);

    __shared__ float red[4][16];
    if (lane == 0) {
#pragma unroll
        for (int c = 0; c < 4; ++c) red[c][wid] = p[c];
    }
    __syncthreads();
    if (h < 4) {
        float s = 0.0f;
#pragma unroll
        for (int w = 0; w < 16; ++w) s += red[h][w];
        out[b * C_OUT + h] = s + out_b[h];
    }
}

// ---------------------------------------------------------------------------
extern "C" void kernel_launch(void* const* d_in, const int* in_sizes, int n_in,
                              void* d_out, int out_size) {
    const float* x1     = (const float*)d_in[0];
    const float* x3     = (const float*)d_in[1];
    const float* conv_w = (const float*)d_in[2];
    const float* conv_b = (const float*)d_in[3];
    const float* bn_g   = (const float*)d_in[4];
    const float* bn_b   = (const float*)d_in[5];
    const float* bn_m   = (const float*)d_in[6];
    const float* bn_v   = (const float*)d_in[7];
    const float* fc_w   = (const float*)d_in[8];
    const float* fc_b   = (const float*)d_in[9];
    const float* out_w  = (const float*)d_in[10];
    const float* out_b  = (const float*)d_in[11];
    float* out = (float*)d_out;

    cudaFuncSetAttribute(gemm_kernel, cudaFuncAttributeMaxDynamicSharedMemorySize, SMEM_BYTES);

    prep_kernel<<<1, 32>>>(conv_w, conv_b, bn_g, bn_b, bn_m, bn_v);
    pre_kernel<<<LDIM, B_SZ>>>(x1);
    dim3 grid(H_DIM / BN, SPLITS);
    gemm_kernel<<<grid, 512, SMEM_BYTES>>>(fc_w, x3);
    head_kernel<<<B_SZ, 512>>>(fc_b, out_w, out_b, out);
}

// round 13
// speedup vs baseline: 2.2101x; 2.2101x over previous
#include <cuda_runtime.h>
#include <cuda_fp16.h>
#include <cstdint>

// Problem constants
#define B_SZ   256
#define LDIM   257                 // N+1
#define M_MAP  66049               // 257*257  (GEMM K)
#define KP     66080               // K padded to multiple of 32
#define H_DIM  512
#define C_OUT  4

// GEMM tiling (legacy fp16 mma m16n8k16)
#define BM 256                     // full batch
#define BN 128                     // 4 N tiles
#define BK 32                      // 2 k16 steps per chunk
#define SPLITS 35                  // 2065 k32-chunks = 35 * 59
#define CPS 59

// smem geometry
#define AROW 40                    // halfs per A row (32 + 8 pad) = 80B, 16B aligned
#define BROW 36                    // floats per B row (32 + 4 pad) = 144B
#define STAGE_BYTES (BM * AROW * 2 + BN * BROW * 4)   // 20480 + 18432 = 38912
#define STAGES 3
#define SMEM_BYTES (STAGES * STAGE_BYTES)       // 116736

// Scratch
__device__ __align__(16) __half g_A[(size_t)B_SZ * KP];                // ~33.8 MB fp16 activations
__device__ __align__(16) float g_part[(size_t)SPLITS * B_SZ * H_DIM];  // ~18.4 MB split-K partials
__device__ float g_consts[5];

__device__ __forceinline__ float frcp(float x) {
    float r; asm("rcp.approx.f32 %0, %1;" : "=f"(r) : "f"(x)); return r;
}
__device__ __forceinline__ float ftanh(float x) {
    float r; asm("tanh.approx.f32 %0, %1;" : "=f"(r) : "f"(x)); return r;
}
__device__ __forceinline__ uint32_t smem_u32(const void* p) {
    return (uint32_t)__cvta_generic_to_shared(p);
}
__device__ __forceinline__ void cp16(uint32_t dst, const void* src) {
    asm volatile("cp.async.cg.shared.global [%0], [%1], 16;\n" :: "r"(dst), "l"(src));
}
// 4-byte cp.async (fp32-safe alignment); src_bytes 0 -> zero-fill
__device__ __forceinline__ void cp4z(uint32_t dst, const float* src, int src_bytes) {
    asm volatile("cp.async.ca.shared.global [%0], [%1], 4, %2;\n" :: "r"(dst), "l"(src), "r"(src_bytes));
}
// pack two fp32 -> half2 (rn) as u32
__device__ __forceinline__ uint32_t pack_h2(float lo, float hi) {
    uint32_t u;
    asm("cvt.rn.f16x2.f32 %0, %1, %2;" : "=r"(u) : "f"(hi), "f"(lo));
    return u;
}

// ---------------------------------------------------------------------------
// Phase 0: fold 1x1-conv + eval-mode BN
// ---------------------------------------------------------------------------
__global__ void prep_kernel(const float* __restrict__ conv_w, const float* __restrict__ conv_b,
                            const float* __restrict__ bn_g,  const float* __restrict__ bn_b,
                            const float* __restrict__ bn_m,  const float* __restrict__ bn_v) {
    if (threadIdx.x == 0) {
        float s = bn_g[0] * rsqrtf(bn_v[0] + 1e-5f);
        g_consts[0] = conv_w[0] * s;
        g_consts[1] = conv_w[1] * s;
        g_consts[2] = conv_w[2] * s;
        g_consts[3] = conv_w[3] * s;
        g_consts[4] = (conv_b[0] - bn_m[0]) * s + bn_b[0];
    }
}

// ---------------------------------------------------------------------------
// Phase 1: activation map -> fp16 via tanh-form sigmoids (4 MUFU/elem).
// sigmoid(x) = 0.5 + 0.5*tanh(x/2); fold the 0.5's into conv consts.
// ---------------------------------------------------------------------------
__global__ void __launch_bounds__(256) act_kernel(const float* __restrict__ x1,
                                                  const float* __restrict__ x3) {
    const int b    = blockIdx.x >> 1;
    const int half = blockIdx.x & 1;
    const int i0 = half ? 129 : 0;
    const int i1 = half ? LDIM : 129;

    __shared__ float sHa[LDIM], sA1[LDIM], sRa[LDIM];

    for (int j = threadIdx.x; j < LDIM; j += 256) {
        const float a0 = (j == 0) ? 0.0f : x1[b * (LDIM - 1) + j - 1];
        const float a1 = (j == 0) ? 1.0f : a0;
        sHa[j] = 0.5f * a0;
        sA1[j] = a1;
        sRa[j] = frcp(a1 + 1e-10f);
    }
    __syncthreads();

    const float c0 = 0.5f * g_consts[0], c1 = 0.5f * g_consts[1];
    const float c2 = 0.5f * g_consts[2], c3 = 0.5f * g_consts[3];
    const float cb = g_consts[4] + c0 + c1 + c2 + c3;   // + 0.5*sum(conv*s)

    for (int i = i0; i < i1; ++i) {
        const float b0 = (i == 0) ? 0.0f : x3[i - 1];
        const float b1 = (i == 0) ? 1.0f : b0;
        const float hb  = 0.5f * b0;
        const float hb1 = 0.5f * b1;
        __half* __restrict__ row = g_A + (size_t)b * KP + (size_t)i * LDIM;

        for (int j = threadIdx.x; j < LDIM; j += 256) {
            const float t1 = ftanh(hb + sHa[j]);        // sigmoid(b0+a0)
            const float t2 = ftanh(hb - sHa[j]);        // sigmoid(b0-a0)
            const float t3 = ftanh(hb1 * sA1[j]);       // sigmoid(b1*a1)
            const float t4 = ftanh(hb1 * sRa[j]);       // sigmoid(b1/(a1+eps))
            float y = cb + c0 * t1 + c1 * t2 + c2 * t3 + c3 * t4;
            y = (y >= 0.0f) ? y : 0.1f * y;             // leaky
            row[j] = __float2half_rn(y);
        }
    }

    if (half == 0 && threadIdx.x < KP - M_MAP)
        g_A[(size_t)b * KP + M_MAP + threadIdx.x] = __float2half_rn(0.0f);
}

// ---------------------------------------------------------------------------
// Phase 2: split-K fp16 GEMM (m16n8k16, fp32 accumulate), cp.async 3-stage.
// 512 threads, 4x4 warp grid, warp tile 64x32. A-frags via ldmatrix.x4.
// ---------------------------------------------------------------------------
__device__ __forceinline__ void mma_f16(float c[4], const uint32_t a[4], const uint32_t b[2]) {
    asm volatile(
        "mma.sync.aligned.m16n8k16.row.col.f32.f16.f16.f32 "
        "{%0,%1,%2,%3}, {%4,%5,%6,%7}, {%8,%9}, {%0,%1,%2,%3};\n"
        : "+f"(c[0]), "+f"(c[1]), "+f"(c[2]), "+f"(c[3])
        : "r"(a[0]), "r"(a[1]), "r"(a[2]), "r"(a[3]), "r"(b[0]), "r"(b[1]));
}

__device__ __forceinline__ void ldsm_x4(uint32_t a[4], uint32_t ptr) {
    asm volatile("ldmatrix.sync.aligned.m8n8.x4.shared.b16 {%0,%1,%2,%3}, [%4];"
                 : "=r"(a[0]), "=r"(a[1]), "=r"(a[2]), "=r"(a[3]) : "r"(ptr));
}

__device__ __forceinline__ void load_chunk(char* sm, int stage, int gchunk, int bn0,
                                           const float* __restrict__ W, int tid) {
    const int k0 = gchunk * BK;
    char* S = sm + stage * STAGE_BYTES;
    uint32_t sA = smem_u32(S);                        // A: BM x AROW halfs
    uint32_t sB = smem_u32(S + BM * AROW * 2);        // B: BN x BROW floats

    // A tile: 256 rows x 32 halfs = 64B/row = 4x16B; 1024 cp16, 2 per thread
#pragma unroll
    for (int r = 0; r < 2; r++) {
        int flat = tid + r * 512;
        int m = flat >> 2, q = flat & 3;              // q: 16B quarter (8 halfs)
        cp16(sA + m * (AROW * 2) + q * 16,
             &g_A[(size_t)m * KP + k0 + q * 8]);
    }
    // B tile: 128 rows x 32 floats = 4096 scalars, 8 per thread (4B, alignment-safe)
#pragma unroll
    for (int r = 0; r < 8; r++) {
        int flat = tid + r * 512;
        int n = flat >> 5, k = flat & 31;
        int ke = k0 + k;
        int bytes = (ke < M_MAP) ? 4 : 0;
        const float* src = &W[(size_t)(bn0 + n) * M_MAP + (bytes ? ke : 0)];
        cp4z(sB + (n * BROW + k) * 4, src, bytes);
    }
}

__global__ void __launch_bounds__(512, 1) gemm_kernel(const float* __restrict__ W) {
    extern __shared__ char sm[];

    const int bn0   = blockIdx.x * BN;     // 4 N tiles
    const int split = blockIdx.y;          // 35 K splits
    const int cbeg  = split * CPS;

    const int tid  = threadIdx.x;
    const int wid  = tid >> 5, lane = tid & 31;
    const int wm   = wid & 3,  wn   = wid >> 2;    // 4 x 4
    const int g    = lane >> 2, tg  = lane & 3;

    // ldmatrix per-lane addressing: lanes 0-15 -> rows 0-15 (col +0),
    // lanes 16-31 -> rows 0-15 (col +8)
    const int ldsmRow = lane & 15;
    const int ldsmCol = (lane >> 4) * 8;

    float acc[4][4][4];
#pragma unroll
    for (int mi = 0; mi < 4; mi++)
#pragma unroll
        for (int ni = 0; ni < 4; ni++)
#pragma unroll
            for (int q = 0; q < 4; q++) acc[mi][ni][q] = 0.0f;

    load_chunk(sm, 0, cbeg + 0, bn0, W, tid);
    asm volatile("cp.async.commit_group;\n" ::: "memory");
    load_chunk(sm, 1, cbeg + 1, bn0, W, tid);
    asm volatile("cp.async.commit_group;\n" ::: "memory");

    for (int cc = 0; cc < CPS; ++cc) {
        asm volatile("cp.async.wait_group 1;\n" ::: "memory");
        __syncthreads();

        if (cc + 2 < CPS)
            load_chunk(sm, (cc + 2) % STAGES, cbeg + cc + 2, bn0, W, tid);
        asm volatile("cp.async.commit_group;\n" ::: "memory");

        char* S = sm + (cc % STAGES) * STAGE_BYTES;
        const float* Sb = reinterpret_cast<const float*>(S + BM * AROW * 2);
        const uint32_t aBase = smem_u32(S) +
            2 * ((wm * 64 + ldsmRow) * AROW + ldsmCol);

#pragma unroll
        for (int ks = 0; ks < 2; ++ks) {               // two k16 steps
            uint32_t a[4][4], bfr[4][2];
#pragma unroll
            for (int mi = 0; mi < 4; mi++)
                ldsm_x4(a[mi], aBase + 2 * (mi * 16 * AROW + ks * 16));
#pragma unroll
            for (int ni = 0; ni < 4; ni++) {
                const int n0 = wn * 32 + ni * 8 + g;
                const int kb = ks * 16 + tg * 2;
                const float2 f01 = *reinterpret_cast<const float2*>(&Sb[n0 * BROW + kb]);
                const float2 f23 = *reinterpret_cast<const float2*>(&Sb[n0 * BROW + kb + 8]);
                bfr[ni][0] = pack_h2(f01.x, f01.y);
                bfr[ni][1] = pack_h2(f23.x, f23.y);
            }
#pragma unroll
            for (int mi = 0; mi < 4; mi++)
#pragma unroll
                for (int ni = 0; ni < 4; ni++)
                    mma_f16(acc[mi][ni], a[mi], bfr[ni]);
        }
    }

    // Deterministic partial store
    float* __restrict__ P = g_part + (size_t)split * (B_SZ * H_DIM);
#pragma unroll
    for (int mi = 0; mi < 4; mi++) {
#pragma unroll
        for (int ni = 0; ni < 4; ni++) {
            const int row = wm * 64 + mi * 16 + g;
            const int col = bn0 + wn * 32 + ni * 8 + tg * 2;
            *reinterpret_cast<float2*>(&P[(size_t)row * H_DIM + col]) =
                make_float2(acc[mi][ni][0], acc[mi][ni][1]);
            *reinterpret_cast<float2*>(&P[(size_t)(row + 8) * H_DIM + col]) =
                make_float2(acc[mi][ni][2], acc[mi][ni][3]);
        }
    }
}

// ---------------------------------------------------------------------------
// Phase 3: reduce 35 splits + bias -> ReLU -> 512->4 head
// ---------------------------------------------------------------------------
__global__ void __launch_bounds__(512) head_kernel(const float* __restrict__ fc_b,
                                                   const float* __restrict__ out_w,
                                                   const float* __restrict__ out_b,
                                                   float* __restrict__ out) {
    const int b = blockIdx.x;
    const int h = threadIdx.x;
    const int wid = h >> 5, lane = h & 31;

    float v = 0.0f;
#pragma unroll
    for (int sp = 0; sp < SPLITS; ++sp)
        v += g_part[(size_t)sp * (B_SZ * H_DIM) + (size_t)b * H_DIM + h];
    v += fc_b[h];
    v = fmaxf(v, 0.0f);

    float p[4];
#pragma unroll
    for (int c = 0; c < 4; ++c) p[c] = v * out_w[c * H_DIM + h];

#pragma unroll
    for (int off = 16; off > 0; off >>= 1)
#pragma unroll
        for (int c = 0; c < 4; ++c) p[c] += __shfl_down_sync(0xffffffffu, p[c], off);

    __shared__ float red[4][16];
    if (lane == 0) {
#pragma unroll
        for (int c = 0; c < 4; ++c) red[c][wid] = p[c];
    }
    __syncthreads();
    if (h < 4) {
        float s = 0.0f;
#pragma unroll
        for (int w = 0; w < 16; ++w) s += red[h][w];
        out[b * C_OUT + h] = s + out_b[h];
    }
}

// ---------------------------------------------------------------------------
extern "C" void kernel_launch(void* const* d_in, const int* in_sizes, int n_in,
                              void* d_out, int out_size) {
    const float* x1     = (const float*)d_in[0];
    const float* x3     = (const float*)d_in[1];
    const float* conv_w = (const float*)d_in[2];
    const float* conv_b = (const float*)d_in[3];
    const float* bn_g   = (const float*)d_in[4];
    const float* bn_b   = (const float*)d_in[5];
    const float* bn_m   = (const float*)d_in[6];
    const float* bn_v   = (const float*)d_in[7];
    const float* fc_w   = (const float*)d_in[8];
    const float* fc_b   = (const float*)d_in[9];
    const float* out_w  = (const float*)d_in[10];
    const float* out_b  = (const float*)d_in[11];
    float* out = (float*)d_out;

    cudaFuncSetAttribute(gemm_kernel, cudaFuncAttributeMaxDynamicSharedMemorySize, SMEM_BYTES);

    prep_kernel<<<1, 32>>>(conv_w, conv_b, bn_g, bn_b, bn_m, bn_v);
    act_kernel<<<B_SZ * 2, 256>>>(x1, x3);
    dim3 grid(H_DIM / BN, SPLITS);
    gemm_kernel<<<grid, 512, SMEM_BYTES>>>(fc_w);
    head_kernel<<<B_SZ, 512>>>(fc_b, out_w, out_b, out);
}

// round 14
// speedup vs baseline: 2.2931x; 1.0375x over previous
#include <cuda_runtime.h>
#include <cuda_fp16.h>
#include <cstdint>

// Problem constants
#define B_SZ   256
#define LDIM   257                 // N+1
#define M_MAP  66049               // 257*257  (GEMM K)
#define KP     66080               // K padded to multiple of 32
#define H_DIM  512
#define C_OUT  4

// GEMM tiling (legacy fp16 mma m16n8k16)
#define BM 256                     // full batch
#define BN 128                     // 4 N tiles
#define BK 32                      // 2 k16 steps per chunk
#define SPLITS 37                  // grid 4*37 = 148 CTAs = one full wave
#define CPS 56                     // ceil(2065/37); last split gets 49
#define TOTAL_CHUNKS 2065

// smem geometry
#define AROW 40                    // halfs per A row (32 + 8 pad) = 80B, 16B aligned
#define BROW 36                    // floats per B row (32 + 4 pad) = 144B
#define STAGE_BYTES (BM * AROW * 2 + BN * BROW * 4)   // 20480 + 18432 = 38912
#define STAGES 3
#define SMEM_BYTES (STAGES * STAGE_BYTES)       // 116736

// Scratch
__device__ __align__(16) __half g_A[(size_t)B_SZ * KP];                // ~33.8 MB fp16 activations
__device__ __align__(16) float g_part[(size_t)SPLITS * B_SZ * H_DIM];  // ~19.4 MB split-K partials
__device__ float g_consts[5];

__device__ __forceinline__ float frcp(float x) {
    float r; asm("rcp.approx.f32 %0, %1;" : "=f"(r) : "f"(x)); return r;
}
__device__ __forceinline__ float ftanh(float x) {
    float r; asm("tanh.approx.f32 %0, %1;" : "=f"(r) : "f"(x)); return r;
}
__device__ __forceinline__ uint32_t smem_u32(const void* p) {
    return (uint32_t)__cvta_generic_to_shared(p);
}
__device__ __forceinline__ void cp16(uint32_t dst, const void* src) {
    asm volatile("cp.async.cg.shared.global [%0], [%1], 16;\n" :: "r"(dst), "l"(src));
}
// 4-byte cp.async (fp32-safe alignment); src_bytes 0 -> zero-fill
__device__ __forceinline__ void cp4z(uint32_t dst, const float* src, int src_bytes) {
    asm volatile("cp.async.ca.shared.global [%0], [%1], 4, %2;\n" :: "r"(dst), "l"(src), "r"(src_bytes));
}
// pack two fp32 -> half2 (rn) as u32
__device__ __forceinline__ uint32_t pack_h2(float lo, float hi) {
    uint32_t u;
    asm("cvt.rn.f16x2.f32 %0, %1, %2;" : "=r"(u) : "f"(hi), "f"(lo));
    return u;
}

// ---------------------------------------------------------------------------
// Phase 0: fold 1x1-conv + eval-mode BN
// ---------------------------------------------------------------------------
__global__ void prep_kernel(const float* __restrict__ conv_w, const float* __restrict__ conv_b,
                            const float* __restrict__ bn_g,  const float* __restrict__ bn_b,
                            const float* __restrict__ bn_m,  const float* __restrict__ bn_v) {
    if (threadIdx.x == 0) {
        float s = bn_g[0] * rsqrtf(bn_v[0] + 1e-5f);
        g_consts[0] = conv_w[0] * s;
        g_consts[1] = conv_w[1] * s;
        g_consts[2] = conv_w[2] * s;
        g_consts[3] = conv_w[3] * s;
        g_consts[4] = (conv_b[0] - bn_m[0]) * s + bn_b[0];
    }
}

// ---------------------------------------------------------------------------
// Phase 1: activation map -> fp16 via tanh-form sigmoids (4 MUFU/elem).
// sigmoid(x) = 0.5 + 0.5*tanh(x/2); fold the 0.5's into conv consts.
// ---------------------------------------------------------------------------
__global__ void __launch_bounds__(256) act_kernel(const float* __restrict__ x1,
                                                  const float* __restrict__ x3) {
    const int b    = blockIdx.x >> 1;
    const int half = blockIdx.x & 1;
    const int i0 = half ? 129 : 0;
    const int i1 = half ? LDIM : 129;

    __shared__ float sHa[LDIM], sA1[LDIM], sRa[LDIM];

    for (int j = threadIdx.x; j < LDIM; j += 256) {
        const float a0 = (j == 0) ? 0.0f : x1[b * (LDIM - 1) + j - 1];
        const float a1 = (j == 0) ? 1.0f : a0;
        sHa[j] = 0.5f * a0;
        sA1[j] = a1;
        sRa[j] = frcp(a1 + 1e-10f);
    }
    __syncthreads();

    const float c0 = 0.5f * g_consts[0], c1 = 0.5f * g_consts[1];
    const float c2 = 0.5f * g_consts[2], c3 = 0.5f * g_consts[3];
    const float cb = g_consts[4] + c0 + c1 + c2 + c3;   // + 0.5*sum(conv*s)

    for (int i = i0; i < i1; ++i) {
        const float b0 = (i == 0) ? 0.0f : x3[i - 1];
        const float b1 = (i == 0) ? 1.0f : b0;
        const float hb  = 0.5f * b0;
        const float hb1 = 0.5f * b1;
        __half* __restrict__ row = g_A + (size_t)b * KP + (size_t)i * LDIM;

        for (int j = threadIdx.x; j < LDIM; j += 256) {
            const float t1 = ftanh(hb + sHa[j]);        // sigmoid(b0+a0)
            const float t2 = ftanh(hb - sHa[j]);        // sigmoid(b0-a0)
            const float t3 = ftanh(hb1 * sA1[j]);       // sigmoid(b1*a1)
            const float t4 = ftanh(hb1 * sRa[j]);       // sigmoid(b1/(a1+eps))
            float y = cb + c0 * t1 + c1 * t2 + c2 * t3 + c3 * t4;
            y = (y >= 0.0f) ? y : 0.1f * y;             // leaky
            row[j] = __float2half_rn(y);
        }
    }

    if (half == 0 && threadIdx.x < KP - M_MAP)
        g_A[(size_t)b * KP + M_MAP + threadIdx.x] = __float2half_rn(0.0f);
}

// ---------------------------------------------------------------------------
// Phase 2: split-K fp16 GEMM (m16n8k16, fp32 accumulate), cp.async 3-stage.
// 512 threads, 4x4 warp grid, warp tile 64x32. A-frags via ldmatrix.x4.
// ---------------------------------------------------------------------------
__device__ __forceinline__ void mma_f16(float c[4], const uint32_t a[4], const uint32_t b[2]) {
    asm volatile(
        "mma.sync.aligned.m16n8k16.row.col.f32.f16.f16.f32 "
        "{%0,%1,%2,%3}, {%4,%5,%6,%7}, {%8,%9}, {%0,%1,%2,%3};\n"
        : "+f"(c[0]), "+f"(c[1]), "+f"(c[2]), "+f"(c[3])
        : "r"(a[0]), "r"(a[1]), "r"(a[2]), "r"(a[3]), "r"(b[0]), "r"(b[1]));
}

__device__ __forceinline__ void ldsm_x4(uint32_t a[4], uint32_t ptr) {
    asm volatile("ldmatrix.sync.aligned.m8n8.x4.shared.b16 {%0,%1,%2,%3}, [%4];"
                 : "=r"(a[0]), "=r"(a[1]), "=r"(a[2]), "=r"(a[3]) : "r"(ptr));
}

__device__ __forceinline__ void load_chunk(char* sm, int stage, int gchunk, int bn0,
                                           const float* __restrict__ W, int tid) {
    const int k0 = gchunk * BK;
    char* S = sm + stage * STAGE_BYTES;
    uint32_t sA = smem_u32(S);                        // A: BM x AROW halfs
    uint32_t sB = smem_u32(S + BM * AROW * 2);        // B: BN x BROW floats

    // A tile: 256 rows x 32 halfs = 64B/row = 4x16B; 1024 cp16, 2 per thread
#pragma unroll
    for (int r = 0; r < 2; r++) {
        int flat = tid + r * 512;
        int m = flat >> 2, q = flat & 3;              // q: 16B quarter (8 halfs)
        cp16(sA + m * (AROW * 2) + q * 16,
             &g_A[(size_t)m * KP + k0 + q * 8]);
    }
    // B tile: 128 rows x 32 floats = 4096 scalars, 8 per thread (4B, alignment-safe)
#pragma unroll
    for (int r = 0; r < 8; r++) {
        int flat = tid + r * 512;
        int n = flat >> 5, k = flat & 31;
        int ke = k0 + k;
        int bytes = (ke < M_MAP) ? 4 : 0;
        const float* src = &W[(size_t)(bn0 + n) * M_MAP + (bytes ? ke : 0)];
        cp4z(sB + (n * BROW + k) * 4, src, bytes);
    }
}

__global__ void __launch_bounds__(512, 1) gemm_kernel(const float* __restrict__ W) {
    extern __shared__ char sm[];

    const int bn0   = blockIdx.x * BN;     // 4 N tiles
    const int split = blockIdx.y;          // 37 K splits
    const int cbeg  = split * CPS;
    const int cend  = (cbeg + CPS < TOTAL_CHUNKS) ? cbeg + CPS : TOTAL_CHUNKS;
    const int nch   = cend - cbeg;

    const int tid  = threadIdx.x;
    const int wid  = tid >> 5, lane = tid & 31;
    const int wm   = wid & 3,  wn   = wid >> 2;    // 4 x 4
    const int g    = lane >> 2, tg  = lane & 3;

    // ldmatrix per-lane addressing: lanes 0-15 -> rows 0-15 (col +0),
    // lanes 16-31 -> rows 0-15 (col +8)
    const int ldsmRow = lane & 15;
    const int ldsmCol = (lane >> 4) * 8;

    float acc[4][4][4];
#pragma unroll
    for (int mi = 0; mi < 4; mi++)
#pragma unroll
        for (int ni = 0; ni < 4; ni++)
#pragma unroll
            for (int q = 0; q < 4; q++) acc[mi][ni][q] = 0.0f;

    load_chunk(sm, 0, cbeg + 0, bn0, W, tid);
    asm volatile("cp.async.commit_group;\n" ::: "memory");
    if (nch > 1)
        load_chunk(sm, 1, cbeg + 1, bn0, W, tid);
    asm volatile("cp.async.commit_group;\n" ::: "memory");

    for (int cc = 0; cc < nch; ++cc) {
        asm volatile("cp.async.wait_group 1;\n" ::: "memory");
        __syncthreads();

        if (cc + 2 < nch)
            load_chunk(sm, (cc + 2) % STAGES, cbeg + cc + 2, bn0, W, tid);
        asm volatile("cp.async.commit_group;\n" ::: "memory");

        char* S = sm + (cc % STAGES) * STAGE_BYTES;
        const float* Sb = reinterpret_cast<const float*>(S + BM * AROW * 2);
        const uint32_t aBase = smem_u32(S) +
            2 * ((wm * 64 + ldsmRow) * AROW + ldsmCol);

#pragma unroll
        for (int ks = 0; ks < 2; ++ks) {               // two k16 steps
            uint32_t a[4][4], bfr[4][2];
#pragma unroll
            for (int mi = 0; mi < 4; mi++)
                ldsm_x4(a[mi], aBase + 2 * (mi * 16 * AROW + ks * 16));
#pragma unroll
            for (int ni = 0; ni < 4; ni++) {
                const int n0 = wn * 32 + ni * 8 + g;
                const int kb = ks * 16 + tg * 2;
                const float2 f01 = *reinterpret_cast<const float2*>(&Sb[n0 * BROW + kb]);
                const float2 f23 = *reinterpret_cast<const float2*>(&Sb[n0 * BROW + kb + 8]);
                bfr[ni][0] = pack_h2(f01.x, f01.y);
                bfr[ni][1] = pack_h2(f23.x, f23.y);
            }
#pragma unroll
            for (int mi = 0; mi < 4; mi++)
#pragma unroll
                for (int ni = 0; ni < 4; ni++)
                    mma_f16(acc[mi][ni], a[mi], bfr[ni]);
        }
    }

    // Deterministic partial store
    float* __restrict__ P = g_part + (size_t)split * (B_SZ * H_DIM);
#pragma unroll
    for (int mi = 0; mi < 4; mi++) {
#pragma unroll
        for (int ni = 0; ni < 4; ni++) {
            const int row = wm * 64 + mi * 16 + g;
            const int col = bn0 + wn * 32 + ni * 8 + tg * 2;
            *reinterpret_cast<float2*>(&P[(size_t)row * H_DIM + col]) =
                make_float2(acc[mi][ni][0], acc[mi][ni][1]);
            *reinterpret_cast<float2*>(&P[(size_t)(row + 8) * H_DIM + col]) =
                make_float2(acc[mi][ni][2], acc[mi][ni][3]);
        }
    }
}

// ---------------------------------------------------------------------------
// Phase 3: reduce 37 splits + bias -> ReLU -> 512->4 head
// ---------------------------------------------------------------------------
__global__ void __launch_bounds__(512) head_kernel(const float* __restrict__ fc_b,
                                                   const float* __restrict__ out_w,
                                                   const float* __restrict__ out_b,
                                                   float* __restrict__ out) {
    const int b = blockIdx.x;
    const int h = threadIdx.x;
    const int wid = h >> 5, lane = h & 31;

    float v = 0.0f;
#pragma unroll
    for (int sp = 0; sp < SPLITS; ++sp)
        v += g_part[(size_t)sp * (B_SZ * H_DIM) + (size_t)b * H_DIM + h];
    v += fc_b[h];
    v = fmaxf(v, 0.0f);

    float p[4];
#pragma unroll
    for (int c = 0; c < 4; ++c) p[c] = v * out_w[c * H_DIM + h];

#pragma unroll
    for (int off = 16; off > 0; off >>= 1)
#pragma unroll
        for (int c = 0; c < 4; ++c) p[c] += __shfl_down_sync(0xffffffffu, p[c], off);

    __shared__ float red[4][16];
    if (lane == 0) {
#pragma unroll
        for (int c = 0; c < 4; ++c) red[c][wid] = p[c];
    }
    __syncthreads();
    if (h < 4) {
        float s = 0.0f;
#pragma unroll
        for (int w = 0; w < 16; ++w) s += red[h][w];
        out[b * C_OUT + h] = s + out_b[h];
    }
}

// ---------------------------------------------------------------------------
extern "C" void kernel_launch(void* const* d_in, const int* in_sizes, int n_in,
                              void* d_out, int out_size) {
    const float* x1     = (const float*)d_in[0];
    const float* x3     = (const float*)d_in[1];
    const float* conv_w = (const float*)d_in[2];
    const float* conv_b = (const float*)d_in[3];
    const float* bn_g   = (const float*)d_in[4];
    const float* bn_b   = (const float*)d_in[5];
    const float* bn_m   = (const float*)d_in[6];
    const float* bn_v   = (const float*)d_in[7];
    const float* fc_w   = (const float*)d_in[8];
    const float* fc_b   = (const float*)d_in[9];
    const float* out_w  = (const float*)d_in[10];
    const float* out_b  = (const float*)d_in[11];
    float* out = (float*)d_out;

    cudaFuncSetAttribute(gemm_kernel, cudaFuncAttributeMaxDynamicSharedMemorySize, SMEM_BYTES);

    prep_kernel<<<1, 32>>>(conv_w, conv_b, bn_g, bn_b, bn_m, bn_v);
    act_kernel<<<B_SZ * 2, 256>>>(x1, x3);
    dim3 grid(H_DIM / BN, SPLITS);
    gemm_kernel<<<grid, 512, SMEM_BYTES>>>(fc_w);
    head_kernel<<<B_SZ, 512>>>(fc_b, out_w, out_b, out);
}